// round 8
// baseline (speedup 1.0000x reference)
#include <cuda_runtime.h>
#include <cuda_bf16.h>
#include <math.h>
#include <stdint.h>

#define BB 4
#define CIN 64
#define HH 128
#define WW 128
#define HWSZ (HH*WW)
#define COUT 64
#define C27 27
#define CK 576  // CIN*9

// ---------------- device scratch (no allocs allowed) ----------------
__device__ __align__(16) float g_om[BB*C27*HWSZ];        // offset-conv out
// main-conv B per tap: [k][oc 64][c 64] bf16 hi/lo
__device__ __align__(16) __nv_bfloat16 g_wBh[9*4096];
__device__ __align__(16) __nv_bfloat16 g_wBl[9*4096];
// offset-conv B per tap: [k][oc 32 (27 padded)][c 64] bf16 hi/lo
__device__ __align__(16) __nv_bfloat16 g_oBh[9*2048];
__device__ __align__(16) __nv_bfloat16 g_oBl[9*2048];

typedef unsigned long long u64;

// ---------------- helpers ----------------
__device__ __forceinline__ uint32_t smem_u32(const void* p) {
    uint32_t a;
    asm("{ .reg .u64 t; cvta.to.shared.u64 t, %1; cvt.u32.u64 %0, t; }" : "=r"(a) : "l"(p));
    return a;
}
__device__ __forceinline__ void cp_async16(uint32_t smem_dst, const void* gsrc) {
    asm volatile("cp.async.cg.shared.global [%0], [%1], 16;" :: "r"(smem_dst), "l"(gsrc));
}
__device__ __forceinline__ void sts128(uint32_t addr, uint32_t r0, uint32_t r1, uint32_t r2, uint32_t r3) {
    asm volatile("st.shared.v4.b32 [%0], {%1, %2, %3, %4};" :: "r"(addr), "r"(r0), "r"(r1), "r"(r2), "r"(r3) : "memory");
}
__device__ __forceinline__ void ldsm4(uint32_t a, uint32_t& r0, uint32_t& r1, uint32_t& r2, uint32_t& r3) {
    asm volatile("ldmatrix.sync.aligned.m8n8.x4.shared.b16 {%0,%1,%2,%3}, [%4];"
                 : "=r"(r0), "=r"(r1), "=r"(r2), "=r"(r3) : "r"(a));
}
__device__ __forceinline__ void mma16816(float* d, const uint32_t* a, const uint32_t* b) {
    asm volatile("mma.sync.aligned.m16n8k16.row.col.f32.bf16.bf16.f32 "
                 "{%0,%1,%2,%3}, {%4,%5,%6,%7}, {%8,%9}, {%0,%1,%2,%3};"
                 : "+f"(d[0]), "+f"(d[1]), "+f"(d[2]), "+f"(d[3])
                 : "r"(a[0]), "r"(a[1]), "r"(a[2]), "r"(a[3]), "r"(b[0]), "r"(b[1]));
}
// split f32 pair -> bf16x2 hi (truncate) + bf16x2 lo (residual, rounded)
__device__ __forceinline__ void split2(float v0, float v1, uint32_t& hi, uint32_t& lo) {
    uint32_t b0 = __float_as_uint(v0) & 0xFFFF0000u;
    uint32_t b1 = __float_as_uint(v1) & 0xFFFF0000u;
    hi = (b0 >> 16) | b1;
    float l0 = v0 - __uint_as_float(b0);
    float l1 = v1 - __uint_as_float(b1);
    asm("cvt.rn.bf16x2.f32 %0, %1, %2;" : "=r"(lo) : "f"(l1), "f"(l0));
}

#define PITCH 144

// ---------------------------------------------------------------------------
// Kernel 0: weight prep -> bf16 hi/lo B tiles for both convs
// ---------------------------------------------------------------------------
__global__ void prep_kernel(const float* __restrict__ wt, const float* __restrict__ owt) {
    int idx = blockIdx.x * blockDim.x + threadIdx.x;    // 144*256 = 36864
    if (idx < 9*4096) {
        int k  = idx >> 12;
        int oc = (idx >> 6) & 63;
        int c  = idx & 63;
        float w = wt[oc*CK + c*9 + k];
        uint32_t wb  = __float_as_uint(w);
        uint32_t hib = wb & 0xFFFF0000u;
        int d = k*4096 + oc*64 + c;
        ((uint16_t*)g_wBh)[d] = (uint16_t)(hib >> 16);
        g_wBl[d] = __float2bfloat16(w - __uint_as_float(hib));
    }
    if (idx < 9*2048) {
        int k  = idx >> 11;
        int oc = (idx >> 6) & 31;
        int c  = idx & 63;
        float w = (oc < C27) ? owt[oc*CK + c*9 + k] : 0.f;
        uint32_t wb  = __float_as_uint(w);
        uint32_t hib = wb & 0xFFFF0000u;
        int d = k*2048 + oc*64 + c;
        ((uint16_t*)g_oBh)[d] = (uint16_t)(hib >> 16);
        g_oBl[d] = __float2bfloat16(w - __uint_as_float(hib));
    }
}

// ---------------------------------------------------------------------------
// Kernel 1: offset/mask conv via mma.sync bf16 3-pass split GEMM.
// (unchanged from R7, known good)
// ---------------------------------------------------------------------------
#define OSM_A_HI 0
#define OSM_A_LO 18432
#define OSM_B    36864
#define OSM_TOT  46080

__global__ __launch_bounds__(256) void offset_mma_kernel(const float* __restrict__ x,
                                                         const float* __restrict__ ob) {
    extern __shared__ __align__(16) char smem[];
    uint32_t sb = smem_u32(smem);
    int tid  = threadIdx.x;
    int lane = tid & 31, wid = tid >> 5;
    int b  = blockIdx.x >> 7;
    int h  = blockIdx.x & 127;
    int px = tid & 127;
    int c0 = (tid >> 7) * 32;

    float acc[4][4] = {};

    const float* xb = x + (size_t)b * CIN * HWSZ;

    int seg = lane >> 3, r8 = lane & 7;
    int m0  = wid * 16;
    uint32_t aBaseH = sb + OSM_A_HI + (uint32_t)((m0 + (seg&1)*8 + r8) * PITCH + (seg>>1)*16);
    uint32_t aBaseL = aBaseH + (OSM_A_LO - OSM_A_HI);
    uint32_t bColB  = (uint32_t)((seg&1)*16);
    uint32_t bRowB  = (uint32_t)(((seg>>1)*8 + r8) * PITCH);

    #pragma unroll 1
    for (int k = 0; k < 9; k++) {
        #pragma unroll
        for (int i = 0; i < 2; i++) {
            int e   = tid + i*256;
            int t8  = e >> 8;
            int cnk = e & 255;
            int row = cnk >> 3, c16 = (cnk & 7) * 16;
            const char* src = (t8 ? (const char*)g_oBl : (const char*)g_oBh)
                              + (size_t)k*4096 + row*128 + c16;
            uint32_t dst = sb + OSM_B + (uint32_t)(t8*4608 + row*PITCH + c16);
            cp_async16(dst, src);
        }
        asm volatile("cp.async.commit_group;");

        int kh = k / 3, kw = k - kh*3;
        int hs = h - 1 + kh;
        int ws = px - 1 + kw;
        bool valid = (hs >= 0) && (hs < HH) && (ws >= 0) && (ws < WW);
        const float* xs = xb + hs*WW + ws;
        #pragma unroll
        for (int g = 0; g < 4; g++) {
            int cc = c0 + g*8;
            float v[8];
            #pragma unroll
            for (int j = 0; j < 8; j++)
                v[j] = valid ? __ldg(xs + (size_t)(cc+j) * HWSZ) : 0.f;
            uint32_t hi[4], lo[4];
            #pragma unroll
            for (int j = 0; j < 4; j++) split2(v[2*j], v[2*j+1], hi[j], lo[j]);
            uint32_t off = (uint32_t)(px*PITCH + cc*2);
            sts128(sb + OSM_A_HI + off, hi[0], hi[1], hi[2], hi[3]);
            sts128(sb + OSM_A_LO + off, lo[0], lo[1], lo[2], lo[3]);
        }

        asm volatile("cp.async.wait_group 0;");
        __syncthreads();

        #pragma unroll
        for (int ks = 0; ks < 4; ks++) {
            uint32_t ah[4], al[4];
            ldsm4(aBaseH + ks*32, ah[0], ah[1], ah[2], ah[3]);
            ldsm4(aBaseL + ks*32, al[0], al[1], al[2], al[3]);
            uint32_t bh[4][2], bl[4][2];
            #pragma unroll
            for (int q = 0; q < 2; q++) {
                uint32_t ra = sb + OSM_B + bRowB + (uint32_t)(q*16*PITCH) + bColB + ks*32;
                ldsm4(ra,        bh[2*q][0], bh[2*q][1], bh[2*q+1][0], bh[2*q+1][1]);
                ldsm4(ra + 4608, bl[2*q][0], bl[2*q][1], bl[2*q+1][0], bl[2*q+1][1]);
            }
            #pragma unroll
            for (int nc = 0; nc < 4; nc++) {
                mma16816(acc[nc], ah, bh[nc]);
                mma16816(acc[nc], ah, bl[nc]);
                mma16816(acc[nc], al, bh[nc]);
            }
        }
        __syncthreads();
    }

    {
        int ml = m0 + (lane >> 2);
        int nf = (lane & 3) * 2;
        float* om = g_om + (size_t)b * C27 * HWSZ + (h << 7) + ml;
        #pragma unroll
        for (int nc = 0; nc < 4; nc++) {
            int n = nc*8 + nf;
            #pragma unroll
            for (int half = 0; half < 2; half++) {
                int nn = n + half;
                if (nn < C27) {
                    float v0 = acc[nc][half]     + __ldg(ob + nn);
                    float v1 = acc[nc][half + 2] + __ldg(ob + nn);
                    if (nn >= 18) {
                        v0 = 1.f / (1.f + __expf(-v0));
                        v1 = 1.f / (1.f + __expf(-v1));
                    }
                    om[(size_t)nn*HWSZ]     = v0;
                    om[(size_t)nn*HWSZ + 8] = v1;
                }
            }
        }
    }
}

// ---------------------------------------------------------------------------
// Kernel 2: deformable conv via mma.sync, software-pipelined:
//  - A tiles double-buffered -> ONE barrier per tap
//  - B tiles double-buffered via cp.async issued post-sync, streamed across tap
//  - om (offsets/mask) prefetched one tap ahead
// Per iteration k: wait B(k); sync; issue B(k+1); produce A(k+1); MMA(k).
// ---------------------------------------------------------------------------
// smem layout: A hi: buf*18432 (0, 18432); A lo: +36864; B hi: 73728 + buf*9216; B lo: +18432
#define DA_LO   36864
#define DB_BASE 73728
#define DB_LO   18432
#define SM_TOT  110592

__global__ __launch_bounds__(256, 2) void dcn_mma_kernel(const float* __restrict__ x,
                                                         const float* __restrict__ bias,
                                                         float* __restrict__ out) {
    extern __shared__ __align__(16) char smem[];
    uint32_t sb = smem_u32(smem);
    int tid  = threadIdx.x;
    int lane = tid & 31, wid = tid >> 5;
    int b  = blockIdx.x >> 7;
    int h  = blockIdx.x & 127;
    int px = tid & 127;
    int c0 = (tid >> 7) * 32;
    int hw = (h << 7) + px;

    float acc[8][4] = {};

    const float* xb  = x + (size_t)b * CIN * HWSZ;
    const float* omb = g_om + (size_t)b * C27 * HWSZ + hw;

    int seg = lane >> 3, r8 = lane & 7;
    int m0  = wid * 16;
    uint32_t aLdsmH = sb + (uint32_t)((m0 + (seg&1)*8 + r8) * PITCH + (seg>>1)*16);
    uint32_t bColB  = (uint32_t)((seg&1)*16);
    uint32_t bRowB  = (uint32_t)(((seg>>1)*8 + r8) * PITCH);

    // ---- helpers as lambdas ----
    auto stageB = [&](int k, int buf) {
        uint32_t bbase = sb + DB_BASE + (uint32_t)buf*9216;
        #pragma unroll
        for (int i = 0; i < 4; i++) {
            int e   = tid + i*256;
            int t8  = e >> 9;
            int cnk = e & 511;
            int row = cnk >> 3, c16 = (cnk & 7) * 16;
            const char* src = (t8 ? (const char*)g_wBl : (const char*)g_wBh)
                              + (size_t)k*8192 + row*128 + c16;
            cp_async16(bbase + (uint32_t)(t8*DB_LO + row*PITCH + c16), src);
        }
        asm volatile("cp.async.commit_group;");
    };

    auto produceA = [&](int k, int buf, float dy, float dx, float m) {
        int kh = k / 3, kw = k - kh*3;
        float hh = (float)(h - 1 + kh) + dy;
        float ww = (float)(px - 1 + kw) + dx;
        float h0f = floorf(hh), w0f = floorf(ww);
        float lh = hh - h0f, lw = ww - w0f;
        int h0 = (int)h0f, w0 = (int)w0f, h1 = h0+1, w1 = w0+1;
        bool vh0 = (h0>=0)&&(h0<HH), vh1 = (h1>=0)&&(h1<HH);
        bool vw0 = (w0>=0)&&(w0<WW), vw1 = (w1>=0)&&(w1<WW);
        int ch0 = min(max(h0,0),HH-1), ch1 = min(max(h1,0),HH-1);
        int cw0 = min(max(w0,0),WW-1), cw1 = min(max(w1,0),WW-1);
        int i00 = ch0*WW+cw0, i01 = ch0*WW+cw1;
        int i10 = ch1*WW+cw0, i11 = ch1*WW+cw1;
        float w00 = (1.f-lh)*(1.f-lw)*m*((vh0&&vw0)?1.f:0.f);
        float w01 = (1.f-lh)*lw      *m*((vh0&&vw1)?1.f:0.f);
        float w10 = lh*(1.f-lw)      *m*((vh1&&vw0)?1.f:0.f);
        float w11 = lh*lw            *m*((vh1&&vw1)?1.f:0.f);

        uint32_t abase = sb + (uint32_t)buf*18432 + (uint32_t)(px*PITCH);
        #pragma unroll 1
        for (int g = 0; g < 4; g++) {
            int cc = c0 + g*8;
            const float* xc = xb + (size_t)cc * HWSZ;
            float v[8];
            #pragma unroll
            for (int j = 0; j < 8; j++) {
                const float* xp = xc + (size_t)j * HWSZ;
                float t = w00 * __ldg(xp + i00);
                t = fmaf(w01, __ldg(xp + i01), t);
                t = fmaf(w10, __ldg(xp + i10), t);
                t = fmaf(w11, __ldg(xp + i11), t);
                v[j] = t;
            }
            uint32_t hi[4], lo[4];
            #pragma unroll
            for (int j = 0; j < 4; j++) split2(v[2*j], v[2*j+1], hi[j], lo[j]);
            sts128(abase + (uint32_t)(cc*2),          hi[0], hi[1], hi[2], hi[3]);
            sts128(abase + (uint32_t)(cc*2) + DA_LO,  lo[0], lo[1], lo[2], lo[3]);
        }
    };

    // ---- prolog: B(0), A(0), om(1) ----
    stageB(0, 0);
    float dyN = __ldg(omb);
    float dxN = __ldg(omb + 9*HWSZ);
    float mN  = __ldg(omb + 18*HWSZ);
    produceA(0, 0, dyN, dxN, mN);
    dyN = __ldg(omb + 1*HWSZ);
    dxN = __ldg(omb + 10*HWSZ);
    mN  = __ldg(omb + 19*HWSZ);

    #pragma unroll 1
    for (int k = 0; k < 9; k++) {
        asm volatile("cp.async.wait_group 0;");   // B(k) landed (only group in flight)
        __syncthreads();                           // A(k) + B(k) visible; A/B alt bufs free

        if (k < 8) {
            stageB(k + 1, (k + 1) & 1);            // streams during production + MMA
            float dy = dyN, dx = dxN, m = mN;
            int kk = (k + 2 <= 8) ? k + 2 : 8;     // prefetch om for tap k+2
            dyN = __ldg(omb + kk*HWSZ);
            dxN = __ldg(omb + (9+kk)*HWSZ);
            mN  = __ldg(omb + (18+kk)*HWSZ);
            produceA(k + 1, (k + 1) & 1, dy, dx, m);
        }

        // ---- MMA(k) ----
        uint32_t aH = aLdsmH + (uint32_t)(k & 1)*18432;
        uint32_t bB = sb + DB_BASE + (uint32_t)(k & 1)*9216 + bRowB + bColB;
        #pragma unroll
        for (int ks = 0; ks < 4; ks++) {
            uint32_t ah[4], al[4];
            ldsm4(aH + ks*32,         ah[0], ah[1], ah[2], ah[3]);
            ldsm4(aH + ks*32 + DA_LO, al[0], al[1], al[2], al[3]);
            uint32_t bh[8][2], bl[8][2];
            #pragma unroll
            for (int q = 0; q < 4; q++) {
                uint32_t ra = bB + (uint32_t)(q*16*PITCH) + ks*32;
                ldsm4(ra,         bh[2*q][0], bh[2*q][1], bh[2*q+1][0], bh[2*q+1][1]);
                ldsm4(ra + DB_LO, bl[2*q][0], bl[2*q][1], bl[2*q+1][0], bl[2*q+1][1]);
            }
            #pragma unroll
            for (int nc = 0; nc < 8; nc++) {
                mma16816(acc[nc], ah, bh[nc]);
                mma16816(acc[nc], ah, bl[nc]);
                mma16816(acc[nc], al, bh[nc]);
            }
        }
    }

    // ---- epilogue ----
    {
        int ml = m0 + (lane >> 2);
        int nf = (lane & 3) * 2;
        float* obp = out + (size_t)b * COUT * HWSZ + (h << 7) + ml;
        #pragma unroll
        for (int nc = 0; nc < 8; nc++) {
            int n = nc*8 + nf;
            float b0 = __ldg(bias + n), b1 = __ldg(bias + n + 1);
            obp[(size_t)n*HWSZ]         = acc[nc][0] + b0;
            obp[(size_t)(n+1)*HWSZ]     = acc[nc][1] + b1;
            obp[(size_t)n*HWSZ + 8]     = acc[nc][2] + b0;
            obp[(size_t)(n+1)*HWSZ + 8] = acc[nc][3] + b1;
        }
    }
}

// ---------------------------------------------------------------------------
extern "C" void kernel_launch(void* const* d_in, const int* in_sizes, int n_in,
                              void* d_out, int out_size) {
    const float* x    = (const float*)d_in[0];  // [4,64,128,128]
    const float* wt   = (const float*)d_in[1];  // [64,64,3,3]
    const float* bias = (const float*)d_in[2];  // [64]
    const float* owt  = (const float*)d_in[3];  // [27,64,3,3]
    const float* ob   = (const float*)d_in[4];  // [27]
    float* out = (float*)d_out;                 // [4,64,128,128]

    cudaFuncSetAttribute(offset_mma_kernel, cudaFuncAttributeMaxDynamicSharedMemorySize, OSM_TOT);
    cudaFuncSetAttribute(dcn_mma_kernel, cudaFuncAttributeMaxDynamicSharedMemorySize, SM_TOT);

    prep_kernel<<<144, 256>>>(wt, owt);
    offset_mma_kernel<<<512, 256, OSM_TOT>>>(x, ob);
    dcn_mma_kernel<<<512, 256, SM_TOT>>>(x, bias, out);
}